// round 7
// baseline (speedup 1.0000x reference)
#include <cuda_runtime.h>
#include <cuda_bf16.h>

// Merged multi-hot embedding bag, sum pooling.
// B=32768, NT=26 tables, 214 packed index columns, DIM=128 fp32.
// Output: [B, 26*128] fp32.
//
// Key change vs R5: rows are loaded as 4x LDG.32 (one 128B line per
// instruction -> 1.0 cyc/wavefront cross-LDG path) instead of 1x LDG.128
// (4 wavefronts within one LDG -> 2.07 cyc/wavefront replay path).
//
// Duration-balanced warp jobs:
//  Heavy block (blockIdx < B): ONE sample, 8 warps:
//    w0..w3 : table 20 quarters (25 hots each), combined via smem
//             (subset barrier: bar.sync 1,128 among warps 0..3 ONLY)
//    w4     : t21 (27)
//    w5     : t19 (12) + t1 (2)
//    w6     : t22 (10) + t10 (3)
//    w7     : t14 (9) + t0 (3)
//  Light block (blockIdx >= B): TWO samples, 4 warps each:
//    v0     : t11 (8) + t3 (2) + single t2
//    v1     : t9 (7) + t15 (5)
//    v2     : t4 (6) + t13 (6)
//    v3     : t23 (3) + 10 singles

#define BATCH 32768
#define NT 26
#define TOTAL_COLS 214
#define DIM 128

// columns of the 10 singles handled by light-warp v3
__constant__ int c_s3col[10] = {14,15,16,17,36,57,58,59,212,213};

// load one 512B row as 4 scalar chunk loads (each = 1 aligned 128B wavefront)
#define LOAD_ROW(i, r0, r1, r2, r3) do {                                   \
    const float* _p = weights + (long long)(i) * DIM + lane;               \
    r0 = __ldg(_p);                                                        \
    r1 = __ldg(_p + 32);                                                   \
    r2 = __ldg(_p + 64);                                                   \
    r3 = __ldg(_p + 96);                                                   \
} while (0)

#define STORE_ROW(t, s0, s1, s2, s3) do {                                  \
    float* _q = orow + (t) * DIM + lane;                                   \
    __stcs(_q,      s0);                                                   \
    __stcs(_q + 32, s1);                                                   \
    __stcs(_q + 64, s2);                                                   \
    __stcs(_q + 96, s3);                                                   \
} while (0)

__device__ __forceinline__ void gather_sum(const int* __restrict__ idxp, int h,
                                           const float* __restrict__ weights, int lane,
                                           float& o0, float& o1, float& o2, float& o3)
{
    // h <= 32: one coalesced index load, broadcast via shfl
    int iv = 0;
    if (lane < h) iv = __ldg(idxp + lane);
    float s0 = 0.f, s1 = 0.f, s2 = 0.f, s3 = 0.f;
    int k = 0;
    for (; k + 4 <= h; k += 4) {
        int i0 = __shfl_sync(0xffffffffu, iv, k);
        int i1 = __shfl_sync(0xffffffffu, iv, k + 1);
        int i2 = __shfl_sync(0xffffffffu, iv, k + 2);
        int i3 = __shfl_sync(0xffffffffu, iv, k + 3);
        float a0, a1, a2, a3, b0, b1, b2, b3;
        float c0, c1, c2, c3, d0, d1, d2, d3;
        LOAD_ROW(i0, a0, a1, a2, a3);
        LOAD_ROW(i1, b0, b1, b2, b3);
        LOAD_ROW(i2, c0, c1, c2, c3);
        LOAD_ROW(i3, d0, d1, d2, d3);
        s0 += (a0 + b0) + (c0 + d0);
        s1 += (a1 + b1) + (c1 + d1);
        s2 += (a2 + b2) + (c2 + d2);
        s3 += (a3 + b3) + (c3 + d3);
    }
    for (; k < h; k++) {
        int i0 = __shfl_sync(0xffffffffu, iv, k);
        float a0, a1, a2, a3;
        LOAD_ROW(i0, a0, a1, a2, a3);
        s0 += a0; s1 += a1; s2 += a2; s3 += a3;
    }
    o0 = s0; o1 = s1; o2 = s2; o3 = s3;
}

__device__ __forceinline__ void bag_store(const int* __restrict__ rowidx, int s, int h,
                                          const float* __restrict__ weights, int lane,
                                          float* __restrict__ orow, int t)
{
    float s0, s1, s2, s3;
    gather_sum(rowidx + s, h, weights, lane, s0, s1, s2, s3);
    STORE_ROW(t, s0, s1, s2, s3);
}

__global__ __launch_bounds__(256, 6)
void merged_embed_bag_kernel(const int* __restrict__ indices,
                             const float* __restrict__ weights,
                             float* __restrict__ out)
{
    __shared__ float4 sp[3][32];   // table-20 partials from warps 1..3

    const int blk  = blockIdx.x;
    const int w    = threadIdx.x >> 5;
    const int lane = threadIdx.x & 31;
    const bool heavy = (blk < BATCH);   // heavy blocks dispatched first

    if (heavy) {
        const int b = blk;
        const int* rowidx = indices + (long long)b * TOTAL_COLS;
        float* orow = out + (long long)b * (NT * DIM);

        if (w < 4) {
            // table 20 quarter: cols [72 + 25*w, 72 + 25*w + 25)
            float s0, s1, s2, s3;
            gather_sum(rowidx + 72 + 25 * w, 25, weights, lane, s0, s1, s2, s3);
            if (w != 0) sp[w - 1][lane] = make_float4(s0, s1, s2, s3);
            // subset barrier: only warps 0..3 (128 threads) participate
            asm volatile("bar.sync 1, 128;" ::: "memory");
            if (w == 0) {
                float4 p0 = sp[0][lane];
                float4 p1 = sp[1][lane];
                float4 p2 = sp[2][lane];
                s0 += (p0.x + p1.x) + p2.x;
                s1 += (p0.y + p1.y) + p2.y;
                s2 += (p0.z + p1.z) + p2.z;
                s3 += (p0.w + p1.w) + p2.w;
                STORE_ROW(20, s0, s1, s2, s3);
            }
        } else if (w == 4) {
            bag_store(rowidx, 172, 27, weights, lane, orow, 21);
        } else if (w == 5) {
            bag_store(rowidx, 60, 12, weights, lane, orow, 19);
            bag_store(rowidx, 3, 2, weights, lane, orow, 1);
        } else if (w == 6) {
            bag_store(rowidx, 199, 10, weights, lane, orow, 22);
            bag_store(rowidx, 25, 3, weights, lane, orow, 10);
        } else {
            bag_store(rowidx, 43, 9, weights, lane, orow, 14);
            bag_store(rowidx, 0, 3, weights, lane, orow, 0);
        }
    } else {
        // light block: two samples, 4 warps each
        const int p = blk - BATCH;
        const int b = (p << 1) | (w >> 2);
        const int v = w & 3;
        const int* rowidx = indices + (long long)b * TOTAL_COLS;
        float* orow = out + (long long)b * (NT * DIM);

        if (v == 0) {
            bag_store(rowidx, 28, 8, weights, lane, orow, 11);
            bag_store(rowidx, 6, 2, weights, lane, orow, 3);
            // single: table 2 at col 5
            int i0 = __ldg(rowidx + 5);
            float a0, a1, a2, a3;
            LOAD_ROW(i0, a0, a1, a2, a3);
            STORE_ROW(2, a0, a1, a2, a3);
        } else if (v == 1) {
            bag_store(rowidx, 18, 7, weights, lane, orow, 9);
            bag_store(rowidx, 52, 5, weights, lane, orow, 15);
        } else if (v == 2) {
            bag_store(rowidx, 8, 6, weights, lane, orow, 4);
            bag_store(rowidx, 37, 6, weights, lane, orow, 13);
        } else {
            bag_store(rowidx, 209, 3, weights, lane, orow, 23);
            // 10 singles: coalesced idx load + shfl, then independent copies
            int iv = 0;
            if (lane < 10) iv = __ldg(rowidx + c_s3col[lane]);
            int i0 = __shfl_sync(0xffffffffu, iv, 0);
            int i1 = __shfl_sync(0xffffffffu, iv, 1);
            int i2 = __shfl_sync(0xffffffffu, iv, 2);
            int i3 = __shfl_sync(0xffffffffu, iv, 3);
            int i4 = __shfl_sync(0xffffffffu, iv, 4);
            {
                float a0, a1, a2, a3, b0, b1, b2, b3, c0, c1, c2, c3, d0, d1, d2, d3;
                LOAD_ROW(i0, a0, a1, a2, a3);
                LOAD_ROW(i1, b0, b1, b2, b3);
                LOAD_ROW(i2, c0, c1, c2, c3);
                LOAD_ROW(i3, d0, d1, d2, d3);
                STORE_ROW(5,  a0, a1, a2, a3);
                STORE_ROW(6,  b0, b1, b2, b3);
                STORE_ROW(7,  c0, c1, c2, c3);
                STORE_ROW(8,  d0, d1, d2, d3);
            }
            int i5 = __shfl_sync(0xffffffffu, iv, 5);
            int i6 = __shfl_sync(0xffffffffu, iv, 6);
            int i7 = __shfl_sync(0xffffffffu, iv, 7);
            int i8 = __shfl_sync(0xffffffffu, iv, 8);
            int i9 = __shfl_sync(0xffffffffu, iv, 9);
            {
                float a0, a1, a2, a3, b0, b1, b2, b3, c0, c1, c2, c3, d0, d1, d2, d3;
                LOAD_ROW(i4, a0, a1, a2, a3);
                LOAD_ROW(i5, b0, b1, b2, b3);
                LOAD_ROW(i6, c0, c1, c2, c3);
                LOAD_ROW(i7, d0, d1, d2, d3);
                STORE_ROW(12, a0, a1, a2, a3);
                STORE_ROW(16, b0, b1, b2, b3);
                STORE_ROW(17, c0, c1, c2, c3);
                STORE_ROW(18, d0, d1, d2, d3);
            }
            {
                float a0, a1, a2, a3, b0, b1, b2, b3;
                LOAD_ROW(i8, a0, a1, a2, a3);
                LOAD_ROW(i9, b0, b1, b2, b3);
                STORE_ROW(24, a0, a1, a2, a3);
                STORE_ROW(25, b0, b1, b2, b3);
            }
        }
    }
}

extern "C" void kernel_launch(void* const* d_in, const int* in_sizes, int n_in,
                              void* d_out, int out_size)
{
    const int* indices = nullptr;
    const float* weights = nullptr;
    const long long idx_elems = (long long)BATCH * TOTAL_COLS;
    for (int i = 0; i < n_in; i++) {
        if ((long long)in_sizes[i] == idx_elems) indices = (const int*)d_in[i];
        else weights = (const float*)d_in[i];
    }
    float* out = (float*)d_out;

    const int threads = 256;
    const int blocks = BATCH + BATCH / 2;   // 32768 heavy + 16384 light = 49152

    merged_embed_bag_kernel<<<blocks, threads>>>(indices, weights, out);
}

// round 8
// speedup vs baseline: 1.2798x; 1.2798x over previous
#include <cuda_runtime.h>
#include <cuda_bf16.h>

// Merged multi-hot embedding bag, sum pooling.
// B=32768, NT=26 tables, 214 packed index columns, DIM=128 fp32.
// Output: [B, 26*128] fp32.
//
// R5 structure (best: 212.7us), occupancy raised to 8 blocks/SM (32-reg budget).
//
// Duration-balanced warp jobs:
//  Heavy block (blockIdx < B): ONE sample, 8 warps:
//    w0..w3 : table 20 quarters (25 hots each), combined via smem
//             (subset barrier: bar.sync 1,128 among warps 0..3 ONLY)
//    w4     : t21 (27)
//    w5     : t19 (12) + t1 (2)
//    w6     : t22 (10) + t10 (3)
//    w7     : t14 (9) + t0 (3)
//  Light block (blockIdx >= B): TWO samples, 4 warps each:
//    v0     : t11 (8) + t3 (2) + single t2
//    v1     : t9 (7) + t15 (5)
//    v2     : t4 (6) + t13 (6)
//    v3     : t23 (3) + 10 singles

#define BATCH 32768
#define NT 26
#define TOTAL_COLS 214
#define DIM 128

// columns of the 10 singles handled by light-warp v3
__constant__ int c_s3col[10] = {14,15,16,17,36,57,58,59,212,213};

#define ROWF4(i) ((const float4*)(weights + (long long)(i) * DIM) + lane)

__device__ __forceinline__ float4 gather_sum(const int* __restrict__ idxp, int h,
                                             const float* __restrict__ weights, int lane)
{
    // h <= 32: one coalesced index load, broadcast via shfl
    int iv = 0;
    if (lane < h) iv = __ldg(idxp + lane);
    float4 acc = make_float4(0.f, 0.f, 0.f, 0.f);
    int k = 0;
    for (; k + 4 <= h; k += 4) {
        int i0 = __shfl_sync(0xffffffffu, iv, k);
        int i1 = __shfl_sync(0xffffffffu, iv, k + 1);
        int i2 = __shfl_sync(0xffffffffu, iv, k + 2);
        int i3 = __shfl_sync(0xffffffffu, iv, k + 3);
        float4 a0 = __ldg(ROWF4(i0));
        float4 a1 = __ldg(ROWF4(i1));
        float4 a2 = __ldg(ROWF4(i2));
        float4 a3 = __ldg(ROWF4(i3));
        acc.x += (a0.x + a1.x) + (a2.x + a3.x);
        acc.y += (a0.y + a1.y) + (a2.y + a3.y);
        acc.z += (a0.z + a1.z) + (a2.z + a3.z);
        acc.w += (a0.w + a1.w) + (a2.w + a3.w);
    }
    for (; k < h; k++) {
        int i0 = __shfl_sync(0xffffffffu, iv, k);
        float4 a0 = __ldg(ROWF4(i0));
        acc.x += a0.x; acc.y += a0.y; acc.z += a0.z; acc.w += a0.w;
    }
    return acc;
}

__device__ __forceinline__ void bag_store(const int* __restrict__ rowidx, int s, int h,
                                          const float* __restrict__ weights, int lane,
                                          float* __restrict__ orow, int t)
{
    float4 acc = gather_sum(rowidx + s, h, weights, lane);
    __stcs((float4*)(orow + t * DIM) + lane, acc);
}

__global__ __launch_bounds__(256, 8)
void merged_embed_bag_kernel(const int* __restrict__ indices,
                             const float* __restrict__ weights,
                             float* __restrict__ out)
{
    __shared__ float4 sp[3][32];   // table-20 partials from warps 1..3

    const int blk  = blockIdx.x;
    const int w    = threadIdx.x >> 5;
    const int lane = threadIdx.x & 31;
    const bool heavy = (blk < BATCH);   // heavy blocks dispatched first

    if (heavy) {
        const int b = blk;
        const int* rowidx = indices + (long long)b * TOTAL_COLS;
        float* orow = out + (long long)b * (NT * DIM);

        if (w < 4) {
            // table 20 quarter: cols [72 + 25*w, 72 + 25*w + 25)
            float4 t20acc = gather_sum(rowidx + 72 + 25 * w, 25, weights, lane);
            if (w != 0) sp[w - 1][lane] = t20acc;
            // subset barrier: only warps 0..3 (128 threads) participate
            asm volatile("bar.sync 1, 128;" ::: "memory");
            if (w == 0) {
                float4 p0 = sp[0][lane];
                float4 p1 = sp[1][lane];
                float4 p2 = sp[2][lane];
                t20acc.x += (p0.x + p1.x) + p2.x;
                t20acc.y += (p0.y + p1.y) + p2.y;
                t20acc.z += (p0.z + p1.z) + p2.z;
                t20acc.w += (p0.w + p1.w) + p2.w;
                __stcs((float4*)(orow + 20 * DIM) + lane, t20acc);
            }
        } else if (w == 4) {
            bag_store(rowidx, 172, 27, weights, lane, orow, 21);
        } else if (w == 5) {
            bag_store(rowidx, 60, 12, weights, lane, orow, 19);
            bag_store(rowidx, 3, 2, weights, lane, orow, 1);
        } else if (w == 6) {
            bag_store(rowidx, 199, 10, weights, lane, orow, 22);
            bag_store(rowidx, 25, 3, weights, lane, orow, 10);
        } else {
            bag_store(rowidx, 43, 9, weights, lane, orow, 14);
            bag_store(rowidx, 0, 3, weights, lane, orow, 0);
        }
    } else {
        // light block: two samples, 4 warps each
        const int p = blk - BATCH;
        const int b = (p << 1) | (w >> 2);
        const int v = w & 3;
        const int* rowidx = indices + (long long)b * TOTAL_COLS;
        float* orow = out + (long long)b * (NT * DIM);

        if (v == 0) {
            bag_store(rowidx, 28, 8, weights, lane, orow, 11);
            bag_store(rowidx, 6, 2, weights, lane, orow, 3);
            // single: table 2 at col 5
            int i0 = __ldg(rowidx + 5);
            float4 a0 = __ldg(ROWF4(i0));
            __stcs((float4*)(orow + 2 * DIM) + lane, a0);
        } else if (v == 1) {
            bag_store(rowidx, 18, 7, weights, lane, orow, 9);
            bag_store(rowidx, 52, 5, weights, lane, orow, 15);
        } else if (v == 2) {
            bag_store(rowidx, 8, 6, weights, lane, orow, 4);
            bag_store(rowidx, 37, 6, weights, lane, orow, 13);
        } else {
            bag_store(rowidx, 209, 3, weights, lane, orow, 23);
            // 10 singles: coalesced idx load + shfl, then 10 independent copies
            int iv = 0;
            if (lane < 10) iv = __ldg(rowidx + c_s3col[lane]);
            int i0 = __shfl_sync(0xffffffffu, iv, 0);
            int i1 = __shfl_sync(0xffffffffu, iv, 1);
            int i2 = __shfl_sync(0xffffffffu, iv, 2);
            int i3 = __shfl_sync(0xffffffffu, iv, 3);
            int i4 = __shfl_sync(0xffffffffu, iv, 4);
            float4 a0 = __ldg(ROWF4(i0));
            float4 a1 = __ldg(ROWF4(i1));
            float4 a2 = __ldg(ROWF4(i2));
            float4 a3 = __ldg(ROWF4(i3));
            float4 a4 = __ldg(ROWF4(i4));
            __stcs((float4*)(orow +  5 * DIM) + lane, a0);
            __stcs((float4*)(orow +  6 * DIM) + lane, a1);
            __stcs((float4*)(orow +  7 * DIM) + lane, a2);
            __stcs((float4*)(orow +  8 * DIM) + lane, a3);
            __stcs((float4*)(orow + 12 * DIM) + lane, a4);
            int i5 = __shfl_sync(0xffffffffu, iv, 5);
            int i6 = __shfl_sync(0xffffffffu, iv, 6);
            int i7 = __shfl_sync(0xffffffffu, iv, 7);
            int i8 = __shfl_sync(0xffffffffu, iv, 8);
            int i9 = __shfl_sync(0xffffffffu, iv, 9);
            float4 a5 = __ldg(ROWF4(i5));
            float4 a6 = __ldg(ROWF4(i6));
            float4 a7 = __ldg(ROWF4(i7));
            float4 a8 = __ldg(ROWF4(i8));
            float4 a9 = __ldg(ROWF4(i9));
            __stcs((float4*)(orow + 16 * DIM) + lane, a5);
            __stcs((float4*)(orow + 17 * DIM) + lane, a6);
            __stcs((float4*)(orow + 18 * DIM) + lane, a7);
            __stcs((float4*)(orow + 24 * DIM) + lane, a8);
            __stcs((float4*)(orow + 25 * DIM) + lane, a9);
        }
    }
}

extern "C" void kernel_launch(void* const* d_in, const int* in_sizes, int n_in,
                              void* d_out, int out_size)
{
    const int* indices = nullptr;
    const float* weights = nullptr;
    const long long idx_elems = (long long)BATCH * TOTAL_COLS;
    for (int i = 0; i < n_in; i++) {
        if ((long long)in_sizes[i] == idx_elems) indices = (const int*)d_in[i];
        else weights = (const float*)d_in[i];
    }
    float* out = (float*)d_out;

    const int threads = 256;
    const int blocks = BATCH + BATCH / 2;   // 32768 heavy + 16384 light = 49152

    merged_embed_bag_kernel<<<blocks, threads>>>(indices, weights, out);
}